// round 10
// baseline (speedup 1.0000x reference)
#include <cuda_runtime.h>
#include <cuda_bf16.h>
#include <cstdint>

#define NN 50000
#define EE 600000
#define GG 512
#define HH 128
#define NB 196          // scan blocks = ceil(NN/256)

// ---------------- scratch (device globals; no allocation allowed) -------------
__device__ float    g_dinv[NN];
__device__ int      g_cnt[NN];
__device__ int      g_off[NN + 1];
__device__ int      g_pos[NN];
__device__ int      g_bsum[256];
__device__ int      g_gstart[GG + 1];
__device__ int      g_csr[EE];
__device__ float    g_h   [NN * HH];
__device__ float    g_agg [NN * HH];
__device__ float    g_gate[NN];
__device__ float    g_pooled[GG * HH];

// ---------------- packed f32x2 helpers (base sm_100+ ISA; FFMA2 in SASS) ------
__device__ __forceinline__ unsigned long long dup_f32x2(float x) {
    unsigned long long r;
    asm("mov.b64 %0, {%1, %1};" : "=l"(r) : "r"(__float_as_uint(x)));
    return r;
}
__device__ __forceinline__ void fma_f32x2(unsigned long long& d,
                                          unsigned long long a,
                                          unsigned long long b) {
    asm("fma.rn.f32x2 %0, %1, %2, %0;" : "+l"(d) : "l"(a), "l"(b));
}
__device__ __forceinline__ float lo_f(unsigned long long v) {
    return __uint_as_float((unsigned)(v & 0xFFFFFFFFull));
}
__device__ __forceinline__ float hi_f(unsigned long long v) {
    return __uint_as_float((unsigned)(v >> 32));
}

// ---------------- GEMM: acc[n,128] = X[n,128] @ W[128,128] --------------------
// 32-row x 128-col tile, 256 threads, 3 CTAs/SM (wave-quantization fix).
// Each thread: 2 rows x 8 cols (f32x2 over col pairs).
// Modes:
//   GW2 == null : Y = acc                       (layer mode; no AGG write)
//   GW2 != null : g_gate[row] = relu(acc+bias_out).GW2 + gb2   (gate mode)
__global__ void __launch_bounds__(256, 3)
k_gemm32(const float* __restrict__ X, const float* __restrict__ W,
         const float* __restrict__ bias_out, float* __restrict__ Y,
         const float* __restrict__ GW2, const float* __restrict__ gb2, int n) {
    __shared__ float XsT[32][36];    // [k][row]
    __shared__ float Ws[32][132];    // [k][col]

    const int tid = threadIdx.x;
    const int tx = tid & 15;          // col group (8 cols)
    const int ty = tid >> 4;          // row pair (2 rows)
    const int tx8 = tx * 8;
    const int row0 = blockIdx.x * 32;

    unsigned long long acc[2][4];
#pragma unroll
    for (int r = 0; r < 2; r++)
#pragma unroll
        for (int c = 0; c < 4; c++) acc[r][c] = 0ull;

    for (int k0 = 0; k0 < 128; k0 += 32) {
        // X tile (32 rows x 32 k) -> transposed XsT[k][row]; 256 float4
        {
            int r = tid >> 3;
            int c4 = tid & 7;
            int gr = row0 + r;
            float4 v = make_float4(0.f, 0.f, 0.f, 0.f);
            if (gr < n) v = ((const float4*)(X + (size_t)gr * 128 + k0))[c4];
            XsT[c4 * 4 + 0][r] = v.x;
            XsT[c4 * 4 + 1][r] = v.y;
            XsT[c4 * 4 + 2][r] = v.z;
            XsT[c4 * 4 + 3][r] = v.w;
        }
        // W tile (32 k x 128 cols); 1024 float4
#pragma unroll
        for (int it = 0; it < 4; it++) {
            int s = tid + it * 256;
            int r = s >> 5;
            int c4 = s & 31;
            float4 v = ((const float4*)(W + (size_t)(k0 + r) * 128))[c4];
            *(float4*)&Ws[r][c4 * 4] = v;
        }
        __syncthreads();

#pragma unroll 8
        for (int kk = 0; kk < 32; kk++) {
            ulonglong2 w01 = *(const ulonglong2*)&Ws[kk][tx8];
            ulonglong2 w23 = *(const ulonglong2*)&Ws[kk][tx8 + 4];
            float2 xv = *(const float2*)&XsT[kk][ty * 2];
            unsigned long long xp0 = dup_f32x2(xv.x);
            unsigned long long xp1 = dup_f32x2(xv.y);
            fma_f32x2(acc[0][0], xp0, w01.x);
            fma_f32x2(acc[0][1], xp0, w01.y);
            fma_f32x2(acc[0][2], xp0, w23.x);
            fma_f32x2(acc[0][3], xp0, w23.y);
            fma_f32x2(acc[1][0], xp1, w01.x);
            fma_f32x2(acc[1][1], xp1, w01.y);
            fma_f32x2(acc[1][2], xp1, w23.x);
            fma_f32x2(acc[1][3], xp1, w23.y);
        }
        __syncthreads();
    }

    if (GW2) {
        // ---- gate epilogue: g_gate[row] = dot(relu(acc+gb1), gw2) + gb2 ----
        float bout[8], w2v[8];
#pragma unroll
        for (int c = 0; c < 8; c++) {
            bout[c] = bias_out[tx8 + c];
            w2v[c] = GW2[tx8 + c];
        }
        float gb2v = gb2[0];
#pragma unroll
        for (int r = 0; r < 2; r++) {
            float o[8];
            o[0] = lo_f(acc[r][0]); o[1] = hi_f(acc[r][0]);
            o[2] = lo_f(acc[r][1]); o[3] = hi_f(acc[r][1]);
            o[4] = lo_f(acc[r][2]); o[5] = hi_f(acc[r][2]);
            o[6] = lo_f(acc[r][3]); o[7] = hi_f(acc[r][3]);
            float dot = 0.0f;
#pragma unroll
            for (int c = 0; c < 8; c++)
                dot += fmaxf(o[c] + bout[c], 0.0f) * w2v[c];
#pragma unroll
            for (int off = 1; off < 16; off <<= 1)
                dot += __shfl_xor_sync(0xFFFFFFFFu, dot, off);
            int row = row0 + ty * 2 + r;
            if (tx == 0 && row < n) g_gate[row] = dot + gb2v;
        }
        return;
    }

    // ---- layer epilogue: Y = acc ----
#pragma unroll
    for (int r = 0; r < 2; r++) {
        int row = row0 + ty * 2 + r;
        if (row >= n) break;
        *(float4*)(Y + (size_t)row * 128 + tx8) =
            make_float4(lo_f(acc[r][0]), hi_f(acc[r][0]),
                        lo_f(acc[r][1]), hi_f(acc[r][1]));
        *(float4*)(Y + (size_t)row * 128 + tx8 + 4) =
            make_float4(lo_f(acc[r][2]), hi_f(acc[r][2]),
                        lo_f(acc[r][3]), hi_f(acc[r][3]));
    }
}

// ---------------- preprocessing ----------------------------------------------
__global__ void k_init() {
    int i = blockIdx.x * blockDim.x + threadIdx.x;
    if (i < NN) g_cnt[i] = 0;
}

__global__ void k_deg(const int* __restrict__ ei) {
    int i = blockIdx.x * blockDim.x + threadIdx.x;
    if (i < EE) atomicAdd(&g_cnt[ei[EE + i]], 1);
}

__global__ void k_scan1() {
    __shared__ int sh[256];
    int i = blockIdx.x * 256 + threadIdx.x;
    int v = (i < NN) ? g_cnt[i] : 0;
    if (i < NN) g_dinv[i] = rsqrtf((float)(v + 1));   // +1 self loop
    sh[threadIdx.x] = v;
    __syncthreads();
    for (int off = 1; off < 256; off <<= 1) {
        int t = (threadIdx.x >= off) ? sh[threadIdx.x - off] : 0;
        __syncthreads();
        sh[threadIdx.x] += t;
        __syncthreads();
    }
    if (i < NN) g_off[i] = sh[threadIdx.x] - v;
    if (threadIdx.x == 255) g_bsum[blockIdx.x] = sh[255];
}

__global__ void k_scan23() {
    __shared__ int sh[256];
    int t = threadIdx.x;
    int v = (t < NB) ? g_bsum[t] : 0;
    sh[t] = v;
    __syncthreads();
    for (int off = 1; off < 256; off <<= 1) {
        int u = (t >= off) ? sh[t - off] : 0;
        __syncthreads();
        sh[t] += u;
        __syncthreads();
    }
    int boff = sh[blockIdx.x] - g_bsum[blockIdx.x];
    __syncthreads();
    int i = blockIdx.x * 256 + t;
    if (i < NN) {
        int o = g_off[i] + boff;
        g_off[i] = o;
        g_pos[i] = o;
    }
    if (i == 0) g_off[NN] = EE;
}

__global__ void k_fill(const int* __restrict__ ei) {
    int e = blockIdx.x * blockDim.x + threadIdx.x;
    if (e >= EE) return;
    int d = ei[EE + e];
    int p = atomicAdd(&g_pos[d], 1);
    g_csr[p] = ei[e];
}

__global__ void k_bound(const int* __restrict__ batch) {
    int i = blockIdx.x * blockDim.x + threadIdx.x;
    if (i >= NN) return;
    int b = batch[i];
    if (i == 0) {
        for (int g = 0; g <= b; g++) g_gstart[g] = 0;
    } else {
        int p = batch[i - 1];
        for (int g = p + 1; g <= b; g++) g_gstart[g] = i;
    }
    if (i == NN - 1) {
        for (int g = b + 1; g <= GG; g++) g_gstart[g] = NN;
    }
}

// ---------------- CSR gather + self term + LayerNorm + ReLU -------------------
// agg[node] = LN_ReLU( bias + h[node]*dinv^2 + sum_in h[s]*dinv[s]*dinv[node] )
__global__ void k_aggcsr(const float* __restrict__ h, float* __restrict__ agg,
                         const float* __restrict__ agg_bias,
                         const float* __restrict__ gamma,
                         const float* __restrict__ beta) {
    int node = blockIdx.x * 8 + (threadIdx.x >> 5);
    int lane = threadIdx.x & 31;
    if (node >= NN) return;

    const float dd = g_dinv[node];
    float4 bv0 = ((const float4*)agg_bias)[lane];
    float4 hn = ((const float4*)h)[(size_t)node * 32 + lane];
    float w2 = dd * dd;
    float4 a0, a1, a2, a3;
    a0.x = bv0.x + hn.x * w2; a0.y = bv0.y + hn.y * w2;
    a0.z = bv0.z + hn.z * w2; a0.w = bv0.w + hn.w * w2;
    a1 = make_float4(0.f, 0.f, 0.f, 0.f);
    a2 = make_float4(0.f, 0.f, 0.f, 0.f);
    a3 = make_float4(0.f, 0.f, 0.f, 0.f);

    int e = g_off[node];
    const int end = g_off[node + 1];

    for (; e + 3 < end; e += 4) {
        int s0 = g_csr[e],     s1 = g_csr[e + 1];
        int s2 = g_csr[e + 2], s3 = g_csr[e + 3];
        float w0 = g_dinv[s0] * dd, w1 = g_dinv[s1] * dd;
        float w2e = g_dinv[s2] * dd, w3 = g_dinv[s3] * dd;
        float4 h0 = ((const float4*)h)[(size_t)s0 * 32 + lane];
        float4 h1 = ((const float4*)h)[(size_t)s1 * 32 + lane];
        float4 h2 = ((const float4*)h)[(size_t)s2 * 32 + lane];
        float4 h3 = ((const float4*)h)[(size_t)s3 * 32 + lane];
        a0.x += h0.x * w0; a0.y += h0.y * w0; a0.z += h0.z * w0; a0.w += h0.w * w0;
        a1.x += h1.x * w1; a1.y += h1.y * w1; a1.z += h1.z * w1; a1.w += h1.w * w1;
        a2.x += h2.x * w2e; a2.y += h2.y * w2e; a2.z += h2.z * w2e; a2.w += h2.w * w2e;
        a3.x += h3.x * w3; a3.y += h3.y * w3; a3.z += h3.z * w3; a3.w += h3.w * w3;
    }
    for (; e < end; e++) {
        int s0 = g_csr[e];
        float w0 = g_dinv[s0] * dd;
        float4 h0 = ((const float4*)h)[(size_t)s0 * 32 + lane];
        a0.x += h0.x * w0; a0.y += h0.y * w0; a0.z += h0.z * w0; a0.w += h0.w * w0;
    }
    a0.x += a1.x + a2.x + a3.x;
    a0.y += a1.y + a2.y + a3.y;
    a0.z += a1.z + a2.z + a3.z;
    a0.w += a1.w + a2.w + a3.w;

    float s = a0.x + a0.y + a0.z + a0.w;
#pragma unroll
    for (int off = 16; off; off >>= 1) s += __shfl_xor_sync(0xFFFFFFFFu, s, off);
    float m = s * (1.0f / 128.0f);
    float dx = a0.x - m, dy = a0.y - m, dz = a0.z - m, dw = a0.w - m;
    float q = dx * dx + dy * dy + dz * dz + dw * dw;
#pragma unroll
    for (int off = 16; off; off >>= 1) q += __shfl_xor_sync(0xFFFFFFFFu, q, off);
    float rinv = rsqrtf(q * (1.0f / 128.0f) + 1e-5f);
    float4 gv = ((const float4*)gamma)[lane];
    float4 bvv = ((const float4*)beta)[lane];
    float4 o;
    o.x = fmaxf(dx * rinv * gv.x + bvv.x, 0.f);
    o.y = fmaxf(dy * rinv * gv.y + bvv.y, 0.f);
    o.z = fmaxf(dz * rinv * gv.z + bvv.z, 0.f);
    o.w = fmaxf(dw * rinv * gv.w + bvv.w, 0.f);
    ((float4*)agg)[(size_t)node * 32 + lane] = o;
}

// ---------------- segment-contiguous attention pooling (block per graph) ------
__global__ void k_poolseg(const float* __restrict__ h) {
    __shared__ float sa[1024];
    __shared__ float red[128];
    const int g = blockIdx.x;
    const int t = threadIdx.x;
    const int s = g_gstart[g];
    const int e = g_gstart[g + 1];

    if (s >= e) {
        g_pooled[(size_t)g * 128 + t] = 0.0f;
        return;
    }

    float m = -3.402823466e+38f;
    for (int i = s + t; i < e; i += 128) m = fmaxf(m, g_gate[i]);
    red[t] = m;
    __syncthreads();
    for (int off = 64; off; off >>= 1) {
        if (t < off) red[t] = fmaxf(red[t], red[t + off]);
        __syncthreads();
    }
    m = red[0];
    __syncthreads();

    float acc = 0.0f;
    float dloc = 0.0f;
    for (int c = s; c < e; c += 1024) {
        int len = min(1024, e - c);
        for (int j = t; j < len; j += 128) {
            float a = expf(g_gate[c + j] - m);
            sa[j] = a;
            dloc += a;
        }
        __syncthreads();
#pragma unroll 4
        for (int j = 0; j < len; j++)
            acc += sa[j] * h[(size_t)(c + j) * 128 + t];
        __syncthreads();
    }
    red[t] = dloc;
    __syncthreads();
    for (int off = 64; off; off >>= 1) {
        if (t < off) red[t] += red[t + off];
        __syncthreads();
    }
    g_pooled[(size_t)g * 128 + t] = acc / red[0];
}

// ---------------- classifier --------------------------------------------------
__global__ void k_cls(const float* __restrict__ cw1, const float* __restrict__ cb1,
                      const float* __restrict__ cw2, const float* __restrict__ cb2,
                      float* __restrict__ out) {
    __shared__ float p[128];
    __shared__ float s0[128];
    __shared__ float s1[128];
    int g = blockIdx.x;
    int t = threadIdx.x;
    p[t] = g_pooled[(size_t)g * 128 + t];
    __syncthreads();
    float acc = cb1[t];
#pragma unroll 8
    for (int k = 0; k < 128; k++) acc += p[k] * cw1[k * 128 + t];
    acc = fmaxf(acc, 0.0f);
    s0[t] = acc * cw2[t * 2 + 0];
    s1[t] = acc * cw2[t * 2 + 1];
    __syncthreads();
    for (int off = 64; off; off >>= 1) {
        if (t < off) { s0[t] += s0[t + off]; s1[t] += s1[t + off]; }
        __syncthreads();
    }
    if (t == 0) {
        out[g * 2 + 0] = s0[0] + cb2[0];
        out[g * 2 + 1] = s1[0] + cb2[1];
    }
}

// ---------------- launch ------------------------------------------------------
extern "C" void kernel_launch(void* const* d_in, const int* in_sizes, int n_in,
                              void* d_out, int out_size) {
    const float* x      = (const float*)d_in[0];
    const int*   ei     = (const int*)  d_in[1];
    const int*   batch  = (const int*)  d_in[2];
    const float* W1     = (const float*)d_in[3];
    const float* b1     = (const float*)d_in[4];
    const float* ln1g   = (const float*)d_in[5];
    const float* ln1b   = (const float*)d_in[6];
    const float* W2     = (const float*)d_in[7];
    const float* b2     = (const float*)d_in[8];
    const float* ln2g   = (const float*)d_in[9];
    const float* ln2b   = (const float*)d_in[10];
    const float* gw1    = (const float*)d_in[11];
    const float* gb1    = (const float*)d_in[12];
    const float* gw2    = (const float*)d_in[13];
    const float* gb2    = (const float*)d_in[14];
    const float* cw1    = (const float*)d_in[15];
    const float* cb1    = (const float*)d_in[16];
    const float* cw2    = (const float*)d_in[17];
    const float* cb2    = (const float*)d_in[18];
    float* out = (float*)d_out;

    float* hbuf;   cudaGetSymbolAddress((void**)&hbuf, g_h);
    float* abuf;   cudaGetSymbolAddress((void**)&abuf, g_agg);

    const int T = 256;
    // ---- preprocessing: degree, dinv, CSR, graph bounds ----
    k_init<<<(NN + T - 1) / T, T>>>();
    k_deg<<<(EE + T - 1) / T, T>>>(ei);
    k_scan1<<<NB, 256>>>();
    k_scan23<<<NB, 256>>>();
    k_fill<<<(EE + T - 1) / T, T>>>(ei);
    k_bound<<<(NN + T - 1) / T, T>>>(batch);

    int gemm_blocks = (NN + 31) / 32;          // 1563
    int agg_blocks  = (NN + 7) / 8;

    // ---- layer 1 ----
    k_gemm32<<<gemm_blocks, T>>>(x, W1, nullptr, hbuf, nullptr, nullptr, NN);
    k_aggcsr<<<agg_blocks, T>>>(hbuf, abuf, b1, ln1g, ln1b);

    // ---- layer 2 ----
    k_gemm32<<<gemm_blocks, T>>>(abuf, W2, nullptr, hbuf, nullptr, nullptr, NN);
    k_aggcsr<<<agg_blocks, T>>>(hbuf, abuf, b2, ln2g, ln2b);

    // ---- attention pooling (gate fused into GEMM; segment pooling) ----
    k_gemm32<<<gemm_blocks, T>>>(abuf, gw1, gb1, nullptr, gw2, gb2, NN);
    k_poolseg<<<GG, 128>>>(abuf);

    // ---- classifier ----
    k_cls<<<GG, 128>>>(cw1, cb1, cw2, cb2, out);
}

// round 12
// speedup vs baseline: 1.8260x; 1.8260x over previous
#include <cuda_runtime.h>
#include <cuda_bf16.h>
#include <cstdint>

#define NN 50000
#define EE 600000
#define GG 512
#define HH 128
#define NB 196          // scan blocks = ceil(NN/256)

// ---------------- scratch (device globals; no allocation allowed) -------------
__device__ float    g_dinv[NN];
__device__ int      g_cnt[NN];
__device__ int      g_off[NN + 1];
__device__ int      g_pos[NN];
__device__ int      g_bsum[256];
__device__ int      g_gstart[GG + 1];
__device__ int      g_csr[EE];
__device__ float    g_h   [NN * HH];
__device__ float    g_agg [NN * HH];
__device__ float    g_gate[NN];
__device__ float    g_pooled[GG * HH];

// ---------------- packed f32x2 helpers (base sm_100+ ISA; FFMA2 in SASS) ------
__device__ __forceinline__ unsigned long long dup_f32x2(float x) {
    unsigned long long r;
    asm("mov.b64 %0, {%1, %1};" : "=l"(r) : "r"(__float_as_uint(x)));
    return r;
}
__device__ __forceinline__ void fma_f32x2(unsigned long long& d,
                                          unsigned long long a,
                                          unsigned long long b) {
    asm("fma.rn.f32x2 %0, %1, %2, %0;" : "+l"(d) : "l"(a), "l"(b));
}
__device__ __forceinline__ float lo_f(unsigned long long v) {
    return __uint_as_float((unsigned)(v & 0xFFFFFFFFull));
}
__device__ __forceinline__ float hi_f(unsigned long long v) {
    return __uint_as_float((unsigned)(v >> 32));
}

// ---------------- GEMM (R5-proven core): Y[n,128] = X[n,128] @ W[128,128] -----
// 128x128 tile, 256 threads, 2 CTAs/SM. Strides 132 (16B-aligned rows).
// Modes:
//   GW2 == null : Y = acc                                   (layer mode)
//   GW2 != null : g_gate[row] = relu(acc+bias_out).GW2 + gb2 (gate mode)
__global__ void __launch_bounds__(256, 2)
k_gemm2(const float* __restrict__ X, const float* __restrict__ W,
        const float* __restrict__ bias_out, float* __restrict__ Y,
        const float* __restrict__ GW2, const float* __restrict__ gb2, int n) {
    __shared__ float XsT[32][132];   // [k][row]
    __shared__ float Ws[32][132];    // [k][col]

    const int tid = threadIdx.x;
    const int tx = tid & 15;          // col group (8 cols)
    const int ty = tid >> 4;          // row group (8 rows)
    const int tx8 = tx * 8, ty8 = ty * 8;
    const int row0 = blockIdx.x * 128;

    unsigned long long acc[8][4];
#pragma unroll
    for (int r = 0; r < 8; r++)
#pragma unroll
        for (int c = 0; c < 4; c++) acc[r][c] = 0ull;

    for (int k0 = 0; k0 < 128; k0 += 32) {
#pragma unroll
        for (int it = 0; it < 4; it++) {
            int s = tid + it * 256;
            int r = s >> 3;
            int c4 = s & 7;
            int gr = row0 + r;
            float4 v = make_float4(0.f, 0.f, 0.f, 0.f);
            if (gr < n) v = ((const float4*)(X + (size_t)gr * 128 + k0))[c4];
            XsT[c4 * 4 + 0][r] = v.x;
            XsT[c4 * 4 + 1][r] = v.y;
            XsT[c4 * 4 + 2][r] = v.z;
            XsT[c4 * 4 + 3][r] = v.w;
        }
#pragma unroll
        for (int it = 0; it < 4; it++) {
            int s = tid + it * 256;
            int r = s >> 5;
            int c4 = s & 31;
            float4 v = ((const float4*)(W + (size_t)(k0 + r) * 128))[c4];
            *(float4*)&Ws[r][c4 * 4] = v;
        }
        __syncthreads();

#pragma unroll 4
        for (int kk = 0; kk < 32; kk++) {
            ulonglong2 w01 = *(const ulonglong2*)&Ws[kk][tx8];
            ulonglong2 w23 = *(const ulonglong2*)&Ws[kk][tx8 + 4];
            float4 xa = *(const float4*)&XsT[kk][ty8];
            float4 xb = *(const float4*)&XsT[kk][ty8 + 4];
            unsigned long long xp[8];
            xp[0] = dup_f32x2(xa.x); xp[1] = dup_f32x2(xa.y);
            xp[2] = dup_f32x2(xa.z); xp[3] = dup_f32x2(xa.w);
            xp[4] = dup_f32x2(xb.x); xp[5] = dup_f32x2(xb.y);
            xp[6] = dup_f32x2(xb.z); xp[7] = dup_f32x2(xb.w);
#pragma unroll
            for (int r = 0; r < 8; r++) {
                fma_f32x2(acc[r][0], xp[r], w01.x);
                fma_f32x2(acc[r][1], xp[r], w01.y);
                fma_f32x2(acc[r][2], xp[r], w23.x);
                fma_f32x2(acc[r][3], xp[r], w23.y);
            }
        }
        __syncthreads();
    }

    if (GW2) {
        float bout[8], w2v[8];
#pragma unroll
        for (int c = 0; c < 8; c++) {
            bout[c] = bias_out[tx8 + c];
            w2v[c] = GW2[tx8 + c];
        }
        float gb2v = gb2[0];
#pragma unroll
        for (int r = 0; r < 8; r++) {
            float o[8];
            o[0] = lo_f(acc[r][0]); o[1] = hi_f(acc[r][0]);
            o[2] = lo_f(acc[r][1]); o[3] = hi_f(acc[r][1]);
            o[4] = lo_f(acc[r][2]); o[5] = hi_f(acc[r][2]);
            o[6] = lo_f(acc[r][3]); o[7] = hi_f(acc[r][3]);
            float dot = 0.0f;
#pragma unroll
            for (int c = 0; c < 8; c++)
                dot += fmaxf(o[c] + bout[c], 0.0f) * w2v[c];
#pragma unroll
            for (int off = 1; off < 16; off <<= 1)
                dot += __shfl_xor_sync(0xFFFFFFFFu, dot, off);
            int row = row0 + ty8 + r;
            if (tx == 0 && row < n) g_gate[row] = dot + gb2v;
        }
        return;
    }

    // ---- layer epilogue: Y = acc only ----
#pragma unroll
    for (int r = 0; r < 8; r++) {
        int row = row0 + ty8 + r;
        if (row >= n) break;
        *(float4*)(Y + (size_t)row * 128 + tx8) =
            make_float4(lo_f(acc[r][0]), hi_f(acc[r][0]),
                        lo_f(acc[r][1]), hi_f(acc[r][1]));
        *(float4*)(Y + (size_t)row * 128 + tx8 + 4) =
            make_float4(lo_f(acc[r][2]), hi_f(acc[r][2]),
                        lo_f(acc[r][3]), hi_f(acc[r][3]));
    }
}

// ---------------- preprocessing ----------------------------------------------
__global__ void k_init() {
    int i = blockIdx.x * blockDim.x + threadIdx.x;
    if (i < NN) g_cnt[i] = 0;
}

__global__ void k_deg(const int* __restrict__ ei) {
    int i = blockIdx.x * blockDim.x + threadIdx.x;
    if (i < EE) atomicAdd(&g_cnt[ei[EE + i]], 1);
}

__global__ void k_scan1() {
    __shared__ int sh[256];
    int i = blockIdx.x * 256 + threadIdx.x;
    int v = (i < NN) ? g_cnt[i] : 0;
    if (i < NN) g_dinv[i] = rsqrtf((float)(v + 1));   // +1 self loop
    sh[threadIdx.x] = v;
    __syncthreads();
    for (int off = 1; off < 256; off <<= 1) {
        int t = (threadIdx.x >= off) ? sh[threadIdx.x - off] : 0;
        __syncthreads();
        sh[threadIdx.x] += t;
        __syncthreads();
    }
    if (i < NN) g_off[i] = sh[threadIdx.x] - v;
    if (threadIdx.x == 255) g_bsum[blockIdx.x] = sh[255];
}

__global__ void k_scan23() {
    __shared__ int sh[256];
    int t = threadIdx.x;
    int v = (t < NB) ? g_bsum[t] : 0;
    sh[t] = v;
    __syncthreads();
    for (int off = 1; off < 256; off <<= 1) {
        int u = (t >= off) ? sh[t - off] : 0;
        __syncthreads();
        sh[t] += u;
        __syncthreads();
    }
    int boff = sh[blockIdx.x] - g_bsum[blockIdx.x];
    __syncthreads();
    int i = blockIdx.x * 256 + t;
    if (i < NN) {
        int o = g_off[i] + boff;
        g_off[i] = o;
        g_pos[i] = o;
    }
    if (i == 0) g_off[NN] = EE;
}

__global__ void k_fill(const int* __restrict__ ei) {
    int e = blockIdx.x * blockDim.x + threadIdx.x;
    if (e >= EE) return;
    int d = ei[EE + e];
    int p = atomicAdd(&g_pos[d], 1);
    g_csr[p] = ei[e];
}

__global__ void k_bound(const int* __restrict__ batch) {
    int i = blockIdx.x * blockDim.x + threadIdx.x;
    if (i >= NN) return;
    int b = batch[i];
    if (i == 0) {
        for (int g = 0; g <= b; g++) g_gstart[g] = 0;
    } else {
        int p = batch[i - 1];
        for (int g = p + 1; g <= b; g++) g_gstart[g] = i;
    }
    if (i == NN - 1) {
        for (int g = b + 1; g <= GG; g++) g_gstart[g] = NN;
    }
}

// ---------------- CSR gather + self term + LayerNorm + ReLU -------------------
// agg[node] = LN_ReLU( bias + h[node]*dinv^2 + sum_in h[s]*dinv[s]*dinv[node] )
__global__ void k_aggcsr(const float* __restrict__ h, float* __restrict__ agg,
                         const float* __restrict__ agg_bias,
                         const float* __restrict__ gamma,
                         const float* __restrict__ beta) {
    int node = blockIdx.x * 8 + (threadIdx.x >> 5);
    int lane = threadIdx.x & 31;
    if (node >= NN) return;

    const float dd = g_dinv[node];
    float4 bv0 = ((const float4*)agg_bias)[lane];
    float4 hn = ((const float4*)h)[(size_t)node * 32 + lane];
    float wself = dd * dd;
    float4 a0, a1, a2, a3;
    a0.x = bv0.x + hn.x * wself; a0.y = bv0.y + hn.y * wself;
    a0.z = bv0.z + hn.z * wself; a0.w = bv0.w + hn.w * wself;
    a1 = make_float4(0.f, 0.f, 0.f, 0.f);
    a2 = make_float4(0.f, 0.f, 0.f, 0.f);
    a3 = make_float4(0.f, 0.f, 0.f, 0.f);

    int e = g_off[node];
    const int end = g_off[node + 1];

    for (; e + 3 < end; e += 4) {
        int s0 = g_csr[e],     s1 = g_csr[e + 1];
        int s2 = g_csr[e + 2], s3 = g_csr[e + 3];
        float w0 = g_dinv[s0] * dd, w1 = g_dinv[s1] * dd;
        float w2 = g_dinv[s2] * dd, w3 = g_dinv[s3] * dd;
        float4 h0 = ((const float4*)h)[(size_t)s0 * 32 + lane];
        float4 h1 = ((const float4*)h)[(size_t)s1 * 32 + lane];
        float4 h2 = ((const float4*)h)[(size_t)s2 * 32 + lane];
        float4 h3 = ((const float4*)h)[(size_t)s3 * 32 + lane];
        a0.x += h0.x * w0; a0.y += h0.y * w0; a0.z += h0.z * w0; a0.w += h0.w * w0;
        a1.x += h1.x * w1; a1.y += h1.y * w1; a1.z += h1.z * w1; a1.w += h1.w * w1;
        a2.x += h2.x * w2; a2.y += h2.y * w2; a2.z += h2.z * w2; a2.w += h2.w * w2;
        a3.x += h3.x * w3; a3.y += h3.y * w3; a3.z += h3.z * w3; a3.w += h3.w * w3;
    }
    for (; e < end; e++) {
        int s0 = g_csr[e];
        float w0 = g_dinv[s0] * dd;
        float4 h0 = ((const float4*)h)[(size_t)s0 * 32 + lane];
        a0.x += h0.x * w0; a0.y += h0.y * w0; a0.z += h0.z * w0; a0.w += h0.w * w0;
    }
    a0.x += a1.x + a2.x + a3.x;
    a0.y += a1.y + a2.y + a3.y;
    a0.z += a1.z + a2.z + a3.z;
    a0.w += a1.w + a2.w + a3.w;

    float s = a0.x + a0.y + a0.z + a0.w;
#pragma unroll
    for (int off = 16; off; off >>= 1) s += __shfl_xor_sync(0xFFFFFFFFu, s, off);
    float m = s * (1.0f / 128.0f);
    float dx = a0.x - m, dy = a0.y - m, dz = a0.z - m, dw = a0.w - m;
    float q = dx * dx + dy * dy + dz * dz + dw * dw;
#pragma unroll
    for (int off = 16; off; off >>= 1) q += __shfl_xor_sync(0xFFFFFFFFu, q, off);
    float rinv = rsqrtf(q * (1.0f / 128.0f) + 1e-5f);
    float4 gv = ((const float4*)gamma)[lane];
    float4 bvv = ((const float4*)beta)[lane];
    float4 o;
    o.x = fmaxf(dx * rinv * gv.x + bvv.x, 0.f);
    o.y = fmaxf(dy * rinv * gv.y + bvv.y, 0.f);
    o.z = fmaxf(dz * rinv * gv.z + bvv.z, 0.f);
    o.w = fmaxf(dw * rinv * gv.w + bvv.w, 0.f);
    ((float4*)agg)[(size_t)node * 32 + lane] = o;
}

// ---------------- segment-contiguous attention pooling (block per graph) ------
__global__ void k_poolseg(const float* __restrict__ h) {
    __shared__ float sa[1024];
    __shared__ float red[128];
    const int g = blockIdx.x;
    const int t = threadIdx.x;
    const int s = g_gstart[g];
    const int e = g_gstart[g + 1];

    if (s >= e) {
        g_pooled[(size_t)g * 128 + t] = 0.0f;
        return;
    }

    float m = -3.402823466e+38f;
    for (int i = s + t; i < e; i += 128) m = fmaxf(m, g_gate[i]);
    red[t] = m;
    __syncthreads();
    for (int off = 64; off; off >>= 1) {
        if (t < off) red[t] = fmaxf(red[t], red[t + off]);
        __syncthreads();
    }
    m = red[0];
    __syncthreads();

    float acc = 0.0f;
    float dloc = 0.0f;
    for (int c = s; c < e; c += 1024) {
        int len = min(1024, e - c);
        for (int j = t; j < len; j += 128) {
            float a = expf(g_gate[c + j] - m);
            sa[j] = a;
            dloc += a;
        }
        __syncthreads();
#pragma unroll 4
        for (int j = 0; j < len; j++)
            acc += sa[j] * h[(size_t)(c + j) * 128 + t];
        __syncthreads();
    }
    red[t] = dloc;
    __syncthreads();
    for (int off = 64; off; off >>= 1) {
        if (t < off) red[t] += red[t + off];
        __syncthreads();
    }
    g_pooled[(size_t)g * 128 + t] = acc / red[0];
}

// ---------------- classifier --------------------------------------------------
__global__ void k_cls(const float* __restrict__ cw1, const float* __restrict__ cb1,
                      const float* __restrict__ cw2, const float* __restrict__ cb2,
                      float* __restrict__ out) {
    __shared__ float p[128];
    __shared__ float s0[128];
    __shared__ float s1[128];
    int g = blockIdx.x;
    int t = threadIdx.x;
    p[t] = g_pooled[(size_t)g * 128 + t];
    __syncthreads();
    float acc = cb1[t];
#pragma unroll 8
    for (int k = 0; k < 128; k++) acc += p[k] * cw1[k * 128 + t];
    acc = fmaxf(acc, 0.0f);
    s0[t] = acc * cw2[t * 2 + 0];
    s1[t] = acc * cw2[t * 2 + 1];
    __syncthreads();
    for (int off = 64; off; off >>= 1) {
        if (t < off) { s0[t] += s0[t + off]; s1[t] += s1[t + off]; }
        __syncthreads();
    }
    if (t == 0) {
        out[g * 2 + 0] = s0[0] + cb2[0];
        out[g * 2 + 1] = s1[0] + cb2[1];
    }
}

// ---------------- launch ------------------------------------------------------
extern "C" void kernel_launch(void* const* d_in, const int* in_sizes, int n_in,
                              void* d_out, int out_size) {
    const float* x      = (const float*)d_in[0];
    const int*   ei     = (const int*)  d_in[1];
    const int*   batch  = (const int*)  d_in[2];
    const float* W1     = (const float*)d_in[3];
    const float* b1     = (const float*)d_in[4];
    const float* ln1g   = (const float*)d_in[5];
    const float* ln1b   = (const float*)d_in[6];
    const float* W2     = (const float*)d_in[7];
    const float* b2     = (const float*)d_in[8];
    const float* ln2g   = (const float*)d_in[9];
    const float* ln2b   = (const float*)d_in[10];
    const float* gw1    = (const float*)d_in[11];
    const float* gb1    = (const float*)d_in[12];
    const float* gw2    = (const float*)d_in[13];
    const float* gb2    = (const float*)d_in[14];
    const float* cw1    = (const float*)d_in[15];
    const float* cb1    = (const float*)d_in[16];
    const float* cw2    = (const float*)d_in[17];
    const float* cb2    = (const float*)d_in[18];
    float* out = (float*)d_out;

    float* hbuf;   cudaGetSymbolAddress((void**)&hbuf, g_h);
    float* abuf;   cudaGetSymbolAddress((void**)&abuf, g_agg);

    const int T = 256;
    // ---- preprocessing: degree, dinv, CSR, graph bounds ----
    k_init<<<(NN + T - 1) / T, T>>>();
    k_deg<<<(EE + T - 1) / T, T>>>(ei);
    k_scan1<<<NB, 256>>>();
    k_scan23<<<NB, 256>>>();
    k_fill<<<(EE + T - 1) / T, T>>>(ei);
    k_bound<<<(NN + T - 1) / T, T>>>(batch);

    int gemm_blocks = (NN + 127) / 128;        // 391
    int agg_blocks  = (NN + 7) / 8;

    // ---- layer 1 ----
    k_gemm2<<<gemm_blocks, T>>>(x, W1, nullptr, hbuf, nullptr, nullptr, NN);
    k_aggcsr<<<agg_blocks, T>>>(hbuf, abuf, b1, ln1g, ln1b);

    // ---- layer 2 ----
    k_gemm2<<<gemm_blocks, T>>>(abuf, W2, nullptr, hbuf, nullptr, nullptr, NN);
    k_aggcsr<<<agg_blocks, T>>>(hbuf, abuf, b2, ln2g, ln2b);

    // ---- attention pooling (gate fused into GEMM; segment pooling) ----
    k_gemm2<<<gemm_blocks, T>>>(abuf, gw1, gb1, nullptr, gw2, gb2, NN);
    k_poolseg<<<GG, 128>>>(abuf);

    // ---- classifier ----
    k_cls<<<GG, 128>>>(cw1, cb1, cw2, cb2, out);
}

// round 13
// speedup vs baseline: 1.9273x; 1.0555x over previous
#include <cuda_runtime.h>
#include <cuda_bf16.h>
#include <cstdint>

#define NN 50000
#define EE 600000
#define GG 512
#define HH 128
#define NB 196          // scan blocks = ceil(NN/256)

// ---------------- scratch (device globals; no allocation allowed) -------------
__device__ float    g_dinv[NN];
__device__ int      g_cnt[NN];
__device__ int      g_off[NN + 1];
__device__ int      g_pos[NN];
__device__ int      g_bsum[256];
__device__ int      g_gstart[GG + 1];
__device__ int      g_csr[EE];
__device__ float    g_h   [NN * HH];
__device__ float    g_agg [NN * HH];
__device__ float    g_gate[NN];
__device__ float    g_pooled[GG * HH];

// ---------------- packed f32x2 helpers (base sm_100+ ISA; FFMA2 in SASS) ------
__device__ __forceinline__ unsigned long long dup_f32x2(float x) {
    unsigned long long r;
    asm("mov.b64 %0, {%1, %1};" : "=l"(r) : "r"(__float_as_uint(x)));
    return r;
}
__device__ __forceinline__ void fma_f32x2(unsigned long long& d,
                                          unsigned long long a,
                                          unsigned long long b) {
    asm("fma.rn.f32x2 %0, %1, %2, %0;" : "+l"(d) : "l"(a), "l"(b));
}
__device__ __forceinline__ float lo_f(unsigned long long v) {
    return __uint_as_float((unsigned)(v & 0xFFFFFFFFull));
}
__device__ __forceinline__ float hi_f(unsigned long long v) {
    return __uint_as_float((unsigned)(v >> 32));
}

// ---------------- GEMM (R5-proven core): Y[n,128] = X[n,128] @ W[128,128] -----
// 128x128 tile, 256 threads, 2 CTAs/SM. Strides 132 (16B-aligned rows).
// Modes:
//   GW2 == null : Y = acc                                   (layer mode)
//   GW2 != null : g_gate[row] = relu(acc+bias_out).GW2 + gb2 (gate mode)
__global__ void __launch_bounds__(256, 2)
k_gemm2(const float* __restrict__ X, const float* __restrict__ W,
        const float* __restrict__ bias_out, float* __restrict__ Y,
        const float* __restrict__ GW2, const float* __restrict__ gb2, int n) {
    __shared__ float XsT[32][132];   // [k][row]
    __shared__ float Ws[32][132];    // [k][col]

    const int tid = threadIdx.x;
    const int tx = tid & 15;          // col group (8 cols)
    const int ty = tid >> 4;          // row group (8 rows)
    const int tx8 = tx * 8, ty8 = ty * 8;
    const int row0 = blockIdx.x * 128;

    unsigned long long acc[8][4];
#pragma unroll
    for (int r = 0; r < 8; r++)
#pragma unroll
        for (int c = 0; c < 4; c++) acc[r][c] = 0ull;

    for (int k0 = 0; k0 < 128; k0 += 32) {
#pragma unroll
        for (int it = 0; it < 4; it++) {
            int s = tid + it * 256;
            int r = s >> 3;
            int c4 = s & 7;
            int gr = row0 + r;
            float4 v = make_float4(0.f, 0.f, 0.f, 0.f);
            if (gr < n) v = ((const float4*)(X + (size_t)gr * 128 + k0))[c4];
            XsT[c4 * 4 + 0][r] = v.x;
            XsT[c4 * 4 + 1][r] = v.y;
            XsT[c4 * 4 + 2][r] = v.z;
            XsT[c4 * 4 + 3][r] = v.w;
        }
#pragma unroll
        for (int it = 0; it < 4; it++) {
            int s = tid + it * 256;
            int r = s >> 5;
            int c4 = s & 31;
            float4 v = ((const float4*)(W + (size_t)(k0 + r) * 128))[c4];
            *(float4*)&Ws[r][c4 * 4] = v;
        }
        __syncthreads();

#pragma unroll 4
        for (int kk = 0; kk < 32; kk++) {
            ulonglong2 w01 = *(const ulonglong2*)&Ws[kk][tx8];
            ulonglong2 w23 = *(const ulonglong2*)&Ws[kk][tx8 + 4];
            float4 xa = *(const float4*)&XsT[kk][ty8];
            float4 xb = *(const float4*)&XsT[kk][ty8 + 4];
            unsigned long long xp[8];
            xp[0] = dup_f32x2(xa.x); xp[1] = dup_f32x2(xa.y);
            xp[2] = dup_f32x2(xa.z); xp[3] = dup_f32x2(xa.w);
            xp[4] = dup_f32x2(xb.x); xp[5] = dup_f32x2(xb.y);
            xp[6] = dup_f32x2(xb.z); xp[7] = dup_f32x2(xb.w);
#pragma unroll
            for (int r = 0; r < 8; r++) {
                fma_f32x2(acc[r][0], xp[r], w01.x);
                fma_f32x2(acc[r][1], xp[r], w01.y);
                fma_f32x2(acc[r][2], xp[r], w23.x);
                fma_f32x2(acc[r][3], xp[r], w23.y);
            }
        }
        __syncthreads();
    }

    if (GW2) {
        float bout[8], w2v[8];
#pragma unroll
        for (int c = 0; c < 8; c++) {
            bout[c] = bias_out[tx8 + c];
            w2v[c] = GW2[tx8 + c];
        }
        float gb2v = gb2[0];
#pragma unroll
        for (int r = 0; r < 8; r++) {
            float o[8];
            o[0] = lo_f(acc[r][0]); o[1] = hi_f(acc[r][0]);
            o[2] = lo_f(acc[r][1]); o[3] = hi_f(acc[r][1]);
            o[4] = lo_f(acc[r][2]); o[5] = hi_f(acc[r][2]);
            o[6] = lo_f(acc[r][3]); o[7] = hi_f(acc[r][3]);
            float dot = 0.0f;
#pragma unroll
            for (int c = 0; c < 8; c++)
                dot += fmaxf(o[c] + bout[c], 0.0f) * w2v[c];
#pragma unroll
            for (int off = 1; off < 16; off <<= 1)
                dot += __shfl_xor_sync(0xFFFFFFFFu, dot, off);
            int row = row0 + ty8 + r;
            if (tx == 0 && row < n) g_gate[row] = dot + gb2v;
        }
        return;
    }

    // ---- layer epilogue: Y = acc only ----
#pragma unroll
    for (int r = 0; r < 8; r++) {
        int row = row0 + ty8 + r;
        if (row >= n) break;
        *(float4*)(Y + (size_t)row * 128 + tx8) =
            make_float4(lo_f(acc[r][0]), hi_f(acc[r][0]),
                        lo_f(acc[r][1]), hi_f(acc[r][1]));
        *(float4*)(Y + (size_t)row * 128 + tx8 + 4) =
            make_float4(lo_f(acc[r][2]), hi_f(acc[r][2]),
                        lo_f(acc[r][3]), hi_f(acc[r][3]));
    }
}

// ---------------- preprocessing ----------------------------------------------
__global__ void k_deg(const int* __restrict__ ei) {
    int i = blockIdx.x * blockDim.x + threadIdx.x;
    if (i < EE) atomicAdd(&g_cnt[ei[EE + i]], 1);
}

__global__ void k_scan1() {
    __shared__ int sh[256];
    int i = blockIdx.x * 256 + threadIdx.x;
    int v = (i < NN) ? g_cnt[i] : 0;
    if (i < NN) g_dinv[i] = rsqrtf((float)(v + 1));   // +1 self loop
    sh[threadIdx.x] = v;
    __syncthreads();
    for (int off = 1; off < 256; off <<= 1) {
        int t = (threadIdx.x >= off) ? sh[threadIdx.x - off] : 0;
        __syncthreads();
        sh[threadIdx.x] += t;
        __syncthreads();
    }
    if (i < NN) g_off[i] = sh[threadIdx.x] - v;
    if (threadIdx.x == 255) g_bsum[blockIdx.x] = sh[255];
}

__global__ void k_scan23() {
    __shared__ int sh[256];
    int t = threadIdx.x;
    int v = (t < NB) ? g_bsum[t] : 0;
    sh[t] = v;
    __syncthreads();
    for (int off = 1; off < 256; off <<= 1) {
        int u = (t >= off) ? sh[t - off] : 0;
        __syncthreads();
        sh[t] += u;
        __syncthreads();
    }
    int boff = sh[blockIdx.x] - g_bsum[blockIdx.x];
    __syncthreads();
    int i = blockIdx.x * 256 + t;
    if (i < NN) {
        int o = g_off[i] + boff;
        g_off[i] = o;
        g_pos[i] = o;
    }
    if (i == 0) g_off[NN] = EE;
}

__global__ void k_fill(const int* __restrict__ ei) {
    int e = blockIdx.x * blockDim.x + threadIdx.x;
    if (e >= EE) return;
    int d = ei[EE + e];
    int p = atomicAdd(&g_pos[d], 1);
    g_csr[p] = ei[e];
}

__global__ void k_bound(const int* __restrict__ batch) {
    int i = blockIdx.x * blockDim.x + threadIdx.x;
    if (i >= NN) return;
    int b = batch[i];
    if (i == 0) {
        for (int g = 0; g <= b; g++) g_gstart[g] = 0;
    } else {
        int p = batch[i - 1];
        for (int g = p + 1; g <= b; g++) g_gstart[g] = i;
    }
    if (i == NN - 1) {
        for (int g = b + 1; g <= GG; g++) g_gstart[g] = NN;
    }
}

// ---------------- CSR gather + self term + LayerNorm + ReLU -------------------
// agg[node] = LN_ReLU( bias + h[node]*dinv^2 + sum_in h[s]*dinv[s]*dinv[node] )
__global__ void k_aggcsr(const float* __restrict__ h, float* __restrict__ agg,
                         const float* __restrict__ agg_bias,
                         const float* __restrict__ gamma,
                         const float* __restrict__ beta) {
    int node = blockIdx.x * 8 + (threadIdx.x >> 5);
    int lane = threadIdx.x & 31;
    if (node >= NN) return;

    const float dd = g_dinv[node];
    float4 bv0 = ((const float4*)agg_bias)[lane];
    float4 hn = ((const float4*)h)[(size_t)node * 32 + lane];
    float wself = dd * dd;
    float4 a0, a1, a2, a3;
    a0.x = bv0.x + hn.x * wself; a0.y = bv0.y + hn.y * wself;
    a0.z = bv0.z + hn.z * wself; a0.w = bv0.w + hn.w * wself;
    a1 = make_float4(0.f, 0.f, 0.f, 0.f);
    a2 = make_float4(0.f, 0.f, 0.f, 0.f);
    a3 = make_float4(0.f, 0.f, 0.f, 0.f);

    int e = g_off[node];
    const int end = g_off[node + 1];

    for (; e + 3 < end; e += 4) {
        int s0 = g_csr[e],     s1 = g_csr[e + 1];
        int s2 = g_csr[e + 2], s3 = g_csr[e + 3];
        float w0 = g_dinv[s0] * dd, w1 = g_dinv[s1] * dd;
        float w2 = g_dinv[s2] * dd, w3 = g_dinv[s3] * dd;
        float4 h0 = ((const float4*)h)[(size_t)s0 * 32 + lane];
        float4 h1 = ((const float4*)h)[(size_t)s1 * 32 + lane];
        float4 h2 = ((const float4*)h)[(size_t)s2 * 32 + lane];
        float4 h3 = ((const float4*)h)[(size_t)s3 * 32 + lane];
        a0.x += h0.x * w0; a0.y += h0.y * w0; a0.z += h0.z * w0; a0.w += h0.w * w0;
        a1.x += h1.x * w1; a1.y += h1.y * w1; a1.z += h1.z * w1; a1.w += h1.w * w1;
        a2.x += h2.x * w2; a2.y += h2.y * w2; a2.z += h2.z * w2; a2.w += h2.w * w2;
        a3.x += h3.x * w3; a3.y += h3.y * w3; a3.z += h3.z * w3; a3.w += h3.w * w3;
    }
    for (; e < end; e++) {
        int s0 = g_csr[e];
        float w0 = g_dinv[s0] * dd;
        float4 h0 = ((const float4*)h)[(size_t)s0 * 32 + lane];
        a0.x += h0.x * w0; a0.y += h0.y * w0; a0.z += h0.z * w0; a0.w += h0.w * w0;
    }
    a0.x += a1.x + a2.x + a3.x;
    a0.y += a1.y + a2.y + a3.y;
    a0.z += a1.z + a2.z + a3.z;
    a0.w += a1.w + a2.w + a3.w;

    float s = a0.x + a0.y + a0.z + a0.w;
#pragma unroll
    for (int off = 16; off; off >>= 1) s += __shfl_xor_sync(0xFFFFFFFFu, s, off);
    float m = s * (1.0f / 128.0f);
    float dx = a0.x - m, dy = a0.y - m, dz = a0.z - m, dw = a0.w - m;
    float q = dx * dx + dy * dy + dz * dz + dw * dw;
#pragma unroll
    for (int off = 16; off; off >>= 1) q += __shfl_xor_sync(0xFFFFFFFFu, q, off);
    float rinv = rsqrtf(q * (1.0f / 128.0f) + 1e-5f);
    float4 gv = ((const float4*)gamma)[lane];
    float4 bvv = ((const float4*)beta)[lane];
    float4 o;
    o.x = fmaxf(dx * rinv * gv.x + bvv.x, 0.f);
    o.y = fmaxf(dy * rinv * gv.y + bvv.y, 0.f);
    o.z = fmaxf(dz * rinv * gv.z + bvv.z, 0.f);
    o.w = fmaxf(dw * rinv * gv.w + bvv.w, 0.f);
    ((float4*)agg)[(size_t)node * 32 + lane] = o;
}

// ---------------- segment-contiguous attention pooling (block per graph) ------
__global__ void k_poolseg(const float* __restrict__ h) {
    __shared__ float sa[1024];
    __shared__ float red[128];
    const int g = blockIdx.x;
    const int t = threadIdx.x;
    const int s = g_gstart[g];
    const int e = g_gstart[g + 1];

    if (s >= e) {
        g_pooled[(size_t)g * 128 + t] = 0.0f;
        return;
    }

    float m = -3.402823466e+38f;
    for (int i = s + t; i < e; i += 128) m = fmaxf(m, g_gate[i]);
    red[t] = m;
    __syncthreads();
    for (int off = 64; off; off >>= 1) {
        if (t < off) red[t] = fmaxf(red[t], red[t + off]);
        __syncthreads();
    }
    m = red[0];
    __syncthreads();

    float acc = 0.0f;
    float dloc = 0.0f;
    for (int c = s; c < e; c += 1024) {
        int len = min(1024, e - c);
        for (int j = t; j < len; j += 128) {
            float a = expf(g_gate[c + j] - m);
            sa[j] = a;
            dloc += a;
        }
        __syncthreads();
#pragma unroll 4
        for (int j = 0; j < len; j++)
            acc += sa[j] * h[(size_t)(c + j) * 128 + t];
        __syncthreads();
    }
    red[t] = dloc;
    __syncthreads();
    for (int off = 64; off; off >>= 1) {
        if (t < off) red[t] += red[t + off];
        __syncthreads();
    }
    g_pooled[(size_t)g * 128 + t] = acc / red[0];
}

// ---------------- classifier --------------------------------------------------
__global__ void k_cls(const float* __restrict__ cw1, const float* __restrict__ cb1,
                      const float* __restrict__ cw2, const float* __restrict__ cb2,
                      float* __restrict__ out) {
    __shared__ float p[128];
    __shared__ float s0[128];
    __shared__ float s1[128];
    int g = blockIdx.x;
    int t = threadIdx.x;
    p[t] = g_pooled[(size_t)g * 128 + t];
    __syncthreads();
    float acc = cb1[t];
#pragma unroll 8
    for (int k = 0; k < 128; k++) acc += p[k] * cw1[k * 128 + t];
    acc = fmaxf(acc, 0.0f);
    s0[t] = acc * cw2[t * 2 + 0];
    s1[t] = acc * cw2[t * 2 + 1];
    __syncthreads();
    for (int off = 64; off; off >>= 1) {
        if (t < off) { s0[t] += s0[t + off]; s1[t] += s1[t + off]; }
        __syncthreads();
    }
    if (t == 0) {
        out[g * 2 + 0] = s0[0] + cb2[0];
        out[g * 2 + 1] = s1[0] + cb2[1];
    }
}

// ---------------- launch ------------------------------------------------------
extern "C" void kernel_launch(void* const* d_in, const int* in_sizes, int n_in,
                              void* d_out, int out_size) {
    const float* x      = (const float*)d_in[0];
    const int*   ei     = (const int*)  d_in[1];
    const int*   batch  = (const int*)  d_in[2];
    const float* W1     = (const float*)d_in[3];
    const float* b1     = (const float*)d_in[4];
    const float* ln1g   = (const float*)d_in[5];
    const float* ln1b   = (const float*)d_in[6];
    const float* W2     = (const float*)d_in[7];
    const float* b2     = (const float*)d_in[8];
    const float* ln2g   = (const float*)d_in[9];
    const float* ln2b   = (const float*)d_in[10];
    const float* gw1    = (const float*)d_in[11];
    const float* gb1    = (const float*)d_in[12];
    const float* gw2    = (const float*)d_in[13];
    const float* gb2    = (const float*)d_in[14];
    const float* cw1    = (const float*)d_in[15];
    const float* cb1    = (const float*)d_in[16];
    const float* cw2    = (const float*)d_in[17];
    const float* cb2    = (const float*)d_in[18];
    float* out = (float*)d_out;

    float* hbuf;   cudaGetSymbolAddress((void**)&hbuf, g_h);
    float* abuf;   cudaGetSymbolAddress((void**)&abuf, g_agg);
    int*   cntp;   cudaGetSymbolAddress((void**)&cntp, g_cnt);

    // streams/events created once on the first (uncaptured) correctness call
    static cudaStream_t s2 = nullptr;
    static cudaEvent_t evFork = nullptr, evJoin = nullptr;
    if (s2 == nullptr) {
        cudaStreamCreateWithFlags(&s2, cudaStreamNonBlocking);
        cudaEventCreateWithFlags(&evFork, cudaEventDisableTiming);
        cudaEventCreateWithFlags(&evJoin, cudaEventDisableTiming);
    }

    const int T = 256;
    int gemm_blocks = (NN + 127) / 128;        // 391
    int agg_blocks  = (NN + 7) / 8;

    // ---- fork: preprocessing on s2, concurrent with GEMM1 on main stream ----
    cudaEventRecord(evFork, 0);
    cudaStreamWaitEvent(s2, evFork, 0);

    cudaMemsetAsync(cntp, 0, NN * sizeof(int), s2);
    k_deg<<<(EE + T - 1) / T, T, 0, s2>>>(ei);
    k_scan1<<<NB, 256, 0, s2>>>();
    k_scan23<<<NB, 256, 0, s2>>>();
    k_fill<<<(EE + T - 1) / T, T, 0, s2>>>(ei);
    k_bound<<<(NN + T - 1) / T, T, 0, s2>>>(batch);
    cudaEventRecord(evJoin, s2);

    // ---- layer 1 GEMM (independent of preprocessing) ----
    k_gemm2<<<gemm_blocks, T>>>(x, W1, nullptr, hbuf, nullptr, nullptr, NN);

    // ---- join: aggcsr needs CSR + dinv ----
    cudaStreamWaitEvent(0, evJoin, 0);
    k_aggcsr<<<agg_blocks, T>>>(hbuf, abuf, b1, ln1g, ln1b);

    // ---- layer 2 ----
    k_gemm2<<<gemm_blocks, T>>>(abuf, W2, nullptr, hbuf, nullptr, nullptr, NN);
    k_aggcsr<<<agg_blocks, T>>>(hbuf, abuf, b2, ln2g, ln2b);

    // ---- attention pooling (gate fused into GEMM; segment pooling) ----
    k_gemm2<<<gemm_blocks, T>>>(abuf, gw1, gb1, nullptr, gw2, gb2, NN);
    k_poolseg<<<GG, 128>>>(abuf);

    // ---- classifier ----
    k_cls<<<GG, 128>>>(cw1, cb1, cw2, cb2, out);
}